// round 1
// baseline (speedup 1.0000x reference)
#include <cuda_runtime.h>
#include <math.h>

#define G      200
#define N0     512
#define NN     (G*N0)        // 102400 nodes at level 1
#define DEG    6
#define ET     (G*N0*DEG)    // 614400 edges
#define K1     410
#define K2     328
#define K3     263
#define FIN    6
#define H      128
#define EPS    1e-5f

// ---------------- device scratch (static, allocation-free) ----------------
__device__ float g_h  [NN*H];     // conv outputs
__device__ float g_hn [NN*H];     // pooled features
__device__ float g_agg[NN*H];     // neighbor aggregation
__device__ float g_score[NN];
__device__ int   g_inv[NN];
__device__ int   g_esrc[ET];
__device__ int   g_edst[ET];
__device__ float g_emask[ET];
__device__ float g_z[G*2*H];      // x1+x2+x3 readout accumulator
__device__ float g_t1[G*H];
__device__ float g_t2[G*64];
__device__ float g_norm[3];

__device__ __forceinline__ float* selbuf(int s) { return s ? g_hn : g_h; }

// ---------------- small utility kernels ----------------
__global__ void k_init_edges(const int* __restrict__ ei) {
    int e = blockIdx.x * blockDim.x + threadIdx.x;
    if (e < ET) {
        g_esrc[e] = ei[e];
        g_edst[e] = ei[ET + e];
        g_emask[e] = 1.0f;
    }
}

__global__ void k_zero_agg(int n) {
    int i = blockIdx.x * blockDim.x + threadIdx.x;
    if (i < n) g_agg[i] = 0.0f;
}

__global__ void k_zero_z() {
    int i = blockIdx.x * blockDim.x + threadIdx.x;
    if (i < G*2*H) g_z[i] = 0.0f;
}

__global__ void k_norms(const float* __restrict__ pw1,
                        const float* __restrict__ pw2,
                        const float* __restrict__ pw3) {
    __shared__ float sh[128];
    int t = threadIdx.x;
    const float* pws[3] = {pw1, pw2, pw3};
    #pragma unroll
    for (int j = 0; j < 3; j++) {
        float v = pws[j][t];
        sh[t] = v * v;
        __syncthreads();
        for (int s = 64; s > 0; s >>= 1) {
            if (t < s) sh[t] += sh[t + s];
            __syncthreads();
        }
        if (t == 0) g_norm[j] = sqrtf(sh[0]);
        __syncthreads();
    }
}

// ---------------- level 1 (F_IN = 6) ----------------
__global__ void k_scatter6(const float* __restrict__ x) {
    int e = blockIdx.x * blockDim.x + threadIdx.x;
    if (e < ET) {
        int s = g_esrc[e] * FIN, d = g_edst[e] * FIN;
        #pragma unroll
        for (int f = 0; f < FIN; f++) atomicAdd(&g_agg[d + f], x[s + f]);
    }
}

__global__ void k_conv1(const float* __restrict__ x,
                        const float* __restrict__ Wrel,
                        const float* __restrict__ Wroot,
                        const float* __restrict__ b) {
    int i = blockIdx.x, o = threadIdx.x;   // blockDim = 128
    __shared__ float sx[FIN], sa[FIN];
    if (o < FIN) { sx[o] = x[i*FIN + o]; sa[o] = g_agg[i*FIN + o]; }
    __syncthreads();
    float acc = b[o];
    #pragma unroll
    for (int f = 0; f < FIN; f++)
        acc += sa[f] * Wrel[o*FIN + f] + sx[f] * Wroot[o*FIN + f];
    g_h[i*H + o] = fmaxf(acc, 0.0f);
}

// ---------------- H=128 scatter + conv (levels 2,3) ----------------
__global__ void k_scatterH(int insel) {
    int e = blockIdx.x;
    if (g_emask[e] == 0.0f) return;
    const float* X = selbuf(insel);
    int f = threadIdx.x;
    atomicAdd(&g_agg[g_edst[e]*H + f], X[g_esrc[e]*H + f]);
}

// C[n,128] = relu( X[n,128] @ Wroot^T + AGG[n,128] @ Wrel^T + b )
// register-tiled implicit GEMM: BM=64 nodes, BN=128 outs, BK=16, 256 thr, 8x4 micro.
__global__ void k_convH(int insel, int outsel, int n,
                        const float* __restrict__ Wrel,
                        const float* __restrict__ Wroot,
                        const float* __restrict__ b) {
    const float* X = selbuf(insel);
    float* Y = selbuf(outsel);
    __shared__ float sA[16][68];    // [k][node], padded: stride 272B (16B-aligned)
    __shared__ float sB[16][132];   // [k][out],  padded: stride 528B (16B-aligned)
    int m0  = blockIdx.x * 64;
    int tid = threadIdx.x;
    int tm  = (tid >> 5) * 8;       // node offset (warp-uniform -> broadcast LDS)
    int tn  = (tid & 31) * 4;       // out offset (float4-friendly)
    float acc[8][4];
    #pragma unroll
    for (int i = 0; i < 8; i++)
        #pragma unroll
        for (int j = 0; j < 4; j++) acc[i][j] = 0.0f;

    for (int kt = 0; kt < 256; kt += 16) {
        // A tile: 64 nodes x 16 k (coalesced: 16 consecutive k per node)
        #pragma unroll
        for (int l = 0; l < 4; l++) {
            int idx = tid + l * 256;        // 0..1023
            int mm = idx >> 4, kk = idx & 15;
            int k = kt + kk;
            int node = m0 + mm;
            float v = 0.0f;
            if (node < n)
                v = (k < 128) ? X[node*H + k] : g_agg[node*H + (k - 128)];
            sA[kk][mm] = v;
        }
        // B tile: 128 outs x 16 k
        #pragma unroll
        for (int l = 0; l < 8; l++) {
            int idx = tid + l * 256;        // 0..2047
            int oo = idx >> 4, kk = idx & 15;
            int k = kt + kk;
            float w = (k < 128) ? Wroot[oo*H + k] : Wrel[oo*H + (k - 128)];
            sB[kk][oo] = w;
        }
        __syncthreads();
        #pragma unroll
        for (int kk = 0; kk < 16; kk++) {
            float4 a0 = *(const float4*)&sA[kk][tm];
            float4 a1 = *(const float4*)&sA[kk][tm + 4];
            float4 bb = *(const float4*)&sB[kk][tn];
            float av[8] = {a0.x,a0.y,a0.z,a0.w,a1.x,a1.y,a1.z,a1.w};
            float bv[4] = {bb.x,bb.y,bb.z,bb.w};
            #pragma unroll
            for (int i = 0; i < 8; i++)
                #pragma unroll
                for (int j = 0; j < 4; j++)
                    acc[i][j] += av[i] * bv[j];
        }
        __syncthreads();
    }
    #pragma unroll
    for (int i = 0; i < 8; i++) {
        int node = m0 + tm + i;
        if (node < n) {
            #pragma unroll
            for (int j = 0; j < 4; j++) {
                float v = acc[i][j] + b[tn + j];
                Y[node*H + tn + j] = fmaxf(v, 0.0f);
            }
        }
    }
}

// ---------------- scoring / topk / remap / readout ----------------
__global__ void k_score(int n, const float* __restrict__ pw, int which) {
    int t = blockIdx.x * blockDim.x + threadIdx.x;
    int w = t >> 5, lane = t & 31;
    if (w >= n) return;
    float acc = 0.0f;
    for (int f = lane; f < H; f += 32) acc += g_h[w*H + f] * pw[f];
    #pragma unroll
    for (int s = 16; s > 0; s >>= 1) acc += __shfl_xor_sync(0xffffffffu, acc, s);
    if (lane == 0) g_score[w] = tanhf(acc / g_norm[which]);
}

// one block (512 thr) per graph: rank-based stable top-k (matches lax.top_k set)
__global__ void k_topk(int insel, int outsel, int n_per, int k) {
    int g = blockIdx.x;
    int tid = threadIdx.x;
    const float* X = selbuf(insel);
    float* Y = selbuf(outsel);
    __shared__ float s[512];
    __shared__ int   rk[512];
    if (tid < n_per) s[tid] = g_score[g*n_per + tid];
    __syncthreads();
    if (tid < n_per) {
        float si = s[tid];
        int r = 0;
        for (int j = 0; j < n_per; j++) {
            float sj = s[j];
            r += (sj > si) || (sj == si && j < tid);
        }
        rk[tid] = r;
        g_inv[g*n_per + tid] = (r < k) ? (g*k + r) : -1;
    }
    __syncthreads();
    int tot = n_per * H;
    for (int idx = tid; idx < tot; idx += 512) {
        int node = idx >> 7;
        int f = idx & 127;
        int r = rk[node];
        if (r < k)
            Y[(g*k + r)*H + f] = X[(g*n_per + node)*H + f] * s[node];
    }
}

__global__ void k_remap() {
    int e = blockIdx.x * blockDim.x + threadIdx.x;
    if (e < ET) {
        int ns = g_inv[g_esrc[e]];
        int nd = g_inv[g_edst[e]];
        float m = g_emask[e];
        if (ns < 0 || nd < 0) m = 0.0f;
        g_esrc[e] = ns < 0 ? 0 : ns;
        g_edst[e] = nd < 0 ? 0 : nd;
        g_emask[e] = m;
    }
}

__global__ void k_readout(int k) {  // reads pooled features in g_hn, accumulates into g_z
    int g = blockIdx.x, f = threadIdx.x;  // 128 threads
    float mx = -INFINITY, sm = 0.0f;
    for (int r = 0; r < k; r++) {
        float v = g_hn[(g*k + r)*H + f];
        mx = fmaxf(mx, v);
        sm += v;
    }
    g_z[g*2*H + f]     += mx;
    g_z[g*2*H + H + f] += sm / (float)k;
}

// ---------------- MLP head ----------------
__global__ void k_fc1(const float* __restrict__ W, const float* __restrict__ b) {
    int r = blockIdx.x, o = threadIdx.x;   // 128 threads
    float acc = b[o];
    for (int f = 0; f < 2*H; f++) acc += g_z[r*2*H + f] * W[o*2*H + f];
    g_t1[r*H + o] = acc;
}

__global__ void k_fc2(const float* __restrict__ W, const float* __restrict__ b) {
    int r = blockIdx.x, o = threadIdx.x;   // 64 threads
    float acc = b[o];
    for (int f = 0; f < H; f++) acc += g_t1[r*H + f] * W[o*H + f];
    g_t2[r*64 + o] = acc;
}

__global__ void k_bn_relu(int sel, const float* __restrict__ gam,
                          const float* __restrict__ bet) {
    int F = sel ? 64 : H;
    float* Xp = sel ? g_t2 : g_t1;
    int f = blockIdx.x;
    int t = threadIdx.x;   // 64 threads
    __shared__ float sh[64];
    float s = 0.0f;
    for (int r = t; r < G; r += 64) s += Xp[r*F + f];
    sh[t] = s; __syncthreads();
    for (int st = 32; st > 0; st >>= 1) { if (t < st) sh[t] += sh[t + st]; __syncthreads(); }
    float mean = sh[0] / (float)G;
    __syncthreads();
    float v = 0.0f;
    for (int r = t; r < G; r += 64) { float d = Xp[r*F + f] - mean; v += d * d; }
    sh[t] = v; __syncthreads();
    for (int st = 32; st > 0; st >>= 1) { if (t < st) sh[t] += sh[t + st]; __syncthreads(); }
    float inv = 1.0f / sqrtf(sh[0] / (float)G + EPS);
    float gg = gam[f], bb = bet[f];
    for (int r = t; r < G; r += 64) {
        float y = (Xp[r*F + f] - mean) * inv * gg + bb;
        Xp[r*F + f] = fmaxf(y, 0.0f);
    }
}

__global__ void k_final(float* __restrict__ out,
                        const float* __restrict__ W,
                        const float* __restrict__ b) {
    int r = blockIdx.x * blockDim.x + threadIdx.x;
    if (r < G) {
        float l0 = b[0], l1 = b[1];
        for (int f = 0; f < 64; f++) {
            float v = g_t2[r*64 + f];
            l0 += v * W[f];
            l1 += v * W[64 + f];
        }
        float m = fmaxf(l0, l1);
        float e0 = expf(l0 - m), e1 = expf(l1 - m);
        float s = e0 + e1;
        out[r*2]     = e0 / s;
        out[r*2 + 1] = e1 / s;
    }
}

// ---------------- launch sequence ----------------
extern "C" void kernel_launch(void* const* d_in, const int* in_sizes, int n_in,
                              void* d_out, int out_size) {
    const float* x      = (const float*)d_in[0];
    const int*   ei     = (const int*)  d_in[1];
    const float* Wrel1  = (const float*)d_in[2];
    const float* Wroot1 = (const float*)d_in[3];
    const float* b1     = (const float*)d_in[4];
    const float* Wrel2  = (const float*)d_in[5];
    const float* Wroot2 = (const float*)d_in[6];
    const float* b2     = (const float*)d_in[7];
    const float* Wrel3  = (const float*)d_in[8];
    const float* Wroot3 = (const float*)d_in[9];
    const float* b3     = (const float*)d_in[10];
    const float* pw1    = (const float*)d_in[11];
    const float* pw2    = (const float*)d_in[12];
    const float* pw3    = (const float*)d_in[13];
    const float* lin1_w = (const float*)d_in[14];
    const float* lin1_b = (const float*)d_in[15];
    const float* lin2_w = (const float*)d_in[16];
    const float* lin2_b = (const float*)d_in[17];
    const float* lin3_w = (const float*)d_in[18];
    const float* lin3_b = (const float*)d_in[19];
    const float* bn1_g  = (const float*)d_in[20];
    const float* bn1_b  = (const float*)d_in[21];
    const float* bn2_g  = (const float*)d_in[22];
    const float* bn2_b  = (const float*)d_in[23];
    float* out = (float*)d_out;

    k_init_edges<<<(ET + 255)/256, 256>>>(ei);
    k_zero_z<<<(G*2*H + 255)/256, 256>>>();
    k_norms<<<1, 128>>>(pw1, pw2, pw3);

    // ----- level 1 -----
    k_zero_agg<<<(NN*FIN + 255)/256, 256>>>(NN*FIN);
    k_scatter6<<<(ET + 255)/256, 256>>>(x);
    k_conv1<<<NN, H>>>(x, Wrel1, Wroot1, b1);
    k_score<<<(NN*32 + 255)/256, 256>>>(NN, pw1, 0);
    k_topk<<<G, 512>>>(0, 1, N0, K1);
    k_remap<<<(ET + 255)/256, 256>>>();
    k_readout<<<G, H>>>(K1);

    // ----- level 2 -----
    const int n2 = G * K1;
    k_zero_agg<<<(n2*H + 255)/256, 256>>>(n2*H);
    k_scatterH<<<ET, H>>>(1);
    k_convH<<<(n2 + 63)/64, 256>>>(1, 0, n2, Wrel2, Wroot2, b2);
    k_score<<<(n2*32 + 255)/256, 256>>>(n2, pw2, 1);
    k_topk<<<G, 512>>>(0, 1, K1, K2);
    k_remap<<<(ET + 255)/256, 256>>>();
    k_readout<<<G, H>>>(K2);

    // ----- level 3 -----
    const int n3 = G * K2;
    k_zero_agg<<<(n3*H + 255)/256, 256>>>(n3*H);
    k_scatterH<<<ET, H>>>(1);
    k_convH<<<(n3 + 63)/64, 256>>>(1, 0, n3, Wrel3, Wroot3, b3);
    k_score<<<(n3*32 + 255)/256, 256>>>(n3, pw3, 2);
    k_topk<<<G, 512>>>(0, 1, K2, K3);
    k_readout<<<G, H>>>(K3);

    // ----- MLP head -----
    k_fc1<<<G, H>>>(lin1_w, lin1_b);
    k_bn_relu<<<H, 64>>>(0, bn1_g, bn1_b);
    k_fc2<<<G, 64>>>(lin2_w, lin2_b);
    k_bn_relu<<<64, 64>>>(1, bn2_g, bn2_b);
    k_final<<<(G + 127)/128, 128>>>(out, lin3_w, lin3_b);
}

// round 2
// speedup vs baseline: 1.6034x; 1.6034x over previous
#include <cuda_runtime.h>
#include <math.h>

#define G      200
#define N0     512
#define NN     (G*N0)        // 102400
#define DEG    6
#define ET     (G*N0*DEG)    // 614400
#define K1     410
#define K2     328
#define K3     263
#define FIN    6
#define H      128
#define EPS    1e-5f

typedef unsigned long long u64;

// ---------------- device scratch ----------------
__device__ float g_h  [NN*H];     // conv outputs (pre-pool)
__device__ float g_hn [NN*H];     // pooled features
__device__ float g_agg[NN*H];     // neighbor aggregation
__device__ float g_score[NN];
__device__ int   g_inv[NN];       // old current id -> new id (or -1) for last pool
__device__ int   g_map[NN];       // orig node -> current id (or -1)
__device__ int   g_perm[NN];      // current id -> orig node
__device__ int   g_csr_off[NN+1];
__device__ int   g_csr_cnt[NN];
__device__ int   g_cur[NN];
__device__ int   g_csr_src[ET];
__device__ int   g_bsum[128];
__device__ float g_z[G*2*H];
__device__ float g_t1[G*H];
__device__ float g_t2[G*64];
__device__ float g_norm[3];

// ---------------- f32x2 helpers ----------------
__device__ __forceinline__ u64 pack2(float x, float y) {
    u64 r; asm("mov.b64 %0,{%1,%2};" : "=l"(r) : "f"(x), "f"(y)); return r;
}
__device__ __forceinline__ u64 fma2(u64 a, u64 b, u64 c) {
    u64 d; asm("fma.rn.f32x2 %0,%1,%2,%3;" : "=l"(d) : "l"(a), "l"(b), "l"(c)); return d;
}
__device__ __forceinline__ float2 unpack2(u64 v) {
    float2 f; asm("mov.b64 {%0,%1},%2;" : "=f"(f.x), "=f"(f.y) : "l"(v)); return f;
}

// ---------------- CSR build ----------------
__global__ void k_zero_int(int* p, int n) {
    int i = blockIdx.x * blockDim.x + threadIdx.x;
    if (i < n) p[i] = 0;
}
__global__ void k_zero_f(float* p, int n) {
    int i = blockIdx.x * blockDim.x + threadIdx.x;
    if (i < n) p[i] = 0.0f;
}
__global__ void k_hist(const int* __restrict__ ei) {
    int e = blockIdx.x * blockDim.x + threadIdx.x;
    if (e < ET) atomicAdd(&g_csr_cnt[ei[ET + e]], 1);
}
__global__ void k_scan1() {   // 100 blocks x 1024
    __shared__ int sh[1024];
    int tid = threadIdx.x;
    int gid = blockIdx.x * 1024 + tid;
    int v = g_csr_cnt[gid];
    sh[tid] = v;
    __syncthreads();
    for (int off = 1; off < 1024; off <<= 1) {
        int t = (tid >= off) ? sh[tid - off] : 0;
        __syncthreads();
        sh[tid] += t;
        __syncthreads();
    }
    g_csr_off[gid] = sh[tid] - v;              // exclusive within block
    if (tid == 1023) g_bsum[blockIdx.x] = sh[tid];
}
__global__ void k_scan2() {   // 1 thread
    int run = 0;
    for (int b = 0; b < 100; b++) { int t = g_bsum[b]; g_bsum[b] = run; run += t; }
    g_csr_off[NN] = ET;
}
__global__ void k_scan3() {   // 100 blocks x 1024
    int gid = blockIdx.x * 1024 + threadIdx.x;
    int v = g_csr_off[gid] + g_bsum[blockIdx.x];
    g_csr_off[gid] = v;
    g_cur[gid] = v;
}
__global__ void k_fill(const int* __restrict__ ei) {
    int e = blockIdx.x * blockDim.x + threadIdx.x;
    if (e < ET) {
        int idx = atomicAdd(&g_cur[ei[ET + e]], 1);
        g_csr_src[idx] = ei[e];
    }
}
__global__ void k_initmaps() {
    int i = blockIdx.x * blockDim.x + threadIdx.x;
    if (i < NN) { g_map[i] = i; g_perm[i] = i; }
}

// ---------------- misc small ----------------
__global__ void k_norms(const float* __restrict__ pw1,
                        const float* __restrict__ pw2,
                        const float* __restrict__ pw3) {
    __shared__ float sh[128];
    int t = threadIdx.x;
    const float* pws[3] = {pw1, pw2, pw3};
    #pragma unroll
    for (int j = 0; j < 3; j++) {
        float v = pws[j][t];
        sh[t] = v * v;
        __syncthreads();
        for (int s = 64; s > 0; s >>= 1) {
            if (t < s) sh[t] += sh[t + s];
            __syncthreads();
        }
        if (t == 0) g_norm[j] = sqrtf(sh[0]);
        __syncthreads();
    }
}

// ---------------- level 1 (F_IN = 6) ----------------
__global__ void k_scatter6(const float* __restrict__ x, const int* __restrict__ ei) {
    int e = blockIdx.x * blockDim.x + threadIdx.x;
    if (e < ET) {
        int s = ei[e] * FIN, d = ei[ET + e] * FIN;
        #pragma unroll
        for (int f = 0; f < FIN; f++) atomicAdd(&g_agg[d + f], x[s + f]);
    }
}

__global__ void k_conv1(const float* __restrict__ x,
                        const float* __restrict__ Wrel,
                        const float* __restrict__ Wroot,
                        const float* __restrict__ b) {
    // 4 nodes per block, 512 threads
    int node = blockIdx.x * 4 + (threadIdx.x >> 7);
    int o = threadIdx.x & 127;
    __shared__ float sx[4][FIN], sa[4][FIN];
    int sub = threadIdx.x >> 7;
    if (o < FIN) { sx[sub][o] = x[node*FIN + o]; sa[sub][o] = g_agg[node*FIN + o]; }
    __syncthreads();
    float acc = b[o];
    #pragma unroll
    for (int f = 0; f < FIN; f++)
        acc += sa[sub][f] * Wrel[o*FIN + f] + sx[sub][f] * Wroot[o*FIN + f];
    g_h[node*H + o] = fmaxf(acc, 0.0f);
}

// ---------------- gather aggregation (levels 2,3) ----------------
// one block (128 thr) per current node; X = g_hn (pooled feats)
__global__ void k_gather() {
    int v = blockIdx.x;
    int f = threadIdx.x;
    int u = g_perm[v];
    int start = g_csr_off[u], end = g_csr_off[u + 1];
    int deg = end - start;
    __shared__ int sw[64];
    int m = deg < 64 ? deg : 64;
    if (f < m) sw[f] = g_map[g_csr_src[start + f]];
    __syncthreads();
    float acc = 0.0f;
    for (int i = 0; i < m; i++) {
        int w = sw[i];
        if (w >= 0) acc += g_hn[w*H + f];
    }
    for (int i = 64; i < deg; i++) {          // practically never taken
        int w = g_map[g_csr_src[start + i]];
        if (w >= 0) acc += g_hn[w*H + f];
    }
    g_agg[v*H + f] = acc;
}

// ---------------- H=128 conv via packed f32x2 ----------------
// Y[n,128] = relu( X@Wroot^T + AGG@Wrel^T + b ), X = g_hn, Y = g_h
__global__ void k_convH(int n,
                        const float* __restrict__ Wrel,
                        const float* __restrict__ Wroot,
                        const float* __restrict__ b) {
    const float* X = g_hn;
    float* Y = g_h;
    __shared__ __align__(16) u64   sA[16][66];   // packed (v,v) per node
    __shared__ __align__(16) float sB[16][132];
    int m0  = blockIdx.x * 64;
    int tid = threadIdx.x;
    int tm  = (tid >> 5) * 8;       // node offset (warp-uniform)
    int tn  = (tid & 31) * 4;       // out offset
    u64 acc[8][2];
    #pragma unroll
    for (int i = 0; i < 8; i++) { acc[i][0] = 0ULL; acc[i][1] = 0ULL; }

    for (int kt = 0; kt < 256; kt += 16) {
        #pragma unroll
        for (int l = 0; l < 4; l++) {
            int idx = tid + l * 256;        // 0..1023
            int mm = idx >> 4, kk = idx & 15;
            int k = kt + kk;
            int node = m0 + mm;
            float v = 0.0f;
            if (node < n)
                v = (k < 128) ? X[node*H + k] : g_agg[node*H + (k - 128)];
            sA[kk][mm] = pack2(v, v);
        }
        #pragma unroll
        for (int l = 0; l < 8; l++) {
            int idx = tid + l * 256;        // 0..2047
            int oo = idx >> 4, kk = idx & 15;
            int k = kt + kk;
            sB[kk][oo] = (k < 128) ? Wroot[oo*H + k] : Wrel[oo*H + (k - 128)];
        }
        __syncthreads();
        #pragma unroll
        for (int kk = 0; kk < 16; kk++) {
            ulonglong2 p0 = *(const ulonglong2*)&sA[kk][tm];
            ulonglong2 p1 = *(const ulonglong2*)&sA[kk][tm + 2];
            ulonglong2 p2 = *(const ulonglong2*)&sA[kk][tm + 4];
            ulonglong2 p3 = *(const ulonglong2*)&sA[kk][tm + 6];
            float4 bb = *(const float4*)&sB[kk][tn];
            u64 b01 = pack2(bb.x, bb.y);
            u64 b23 = pack2(bb.z, bb.w);
            u64 av[8] = {p0.x, p0.y, p1.x, p1.y, p2.x, p2.y, p3.x, p3.y};
            #pragma unroll
            for (int i = 0; i < 8; i++) {
                acc[i][0] = fma2(av[i], b01, acc[i][0]);
                acc[i][1] = fma2(av[i], b23, acc[i][1]);
            }
        }
        __syncthreads();
    }
    float4 bb4 = *(const float4*)&b[tn];
    #pragma unroll
    for (int i = 0; i < 8; i++) {
        int node = m0 + tm + i;
        if (node < n) {
            float2 v0 = unpack2(acc[i][0]);
            float2 v1 = unpack2(acc[i][1]);
            float4 o;
            o.x = fmaxf(v0.x + bb4.x, 0.0f);
            o.y = fmaxf(v0.y + bb4.y, 0.0f);
            o.z = fmaxf(v1.x + bb4.z, 0.0f);
            o.w = fmaxf(v1.y + bb4.w, 0.0f);
            *(float4*)&Y[node*H + tn] = o;
        }
    }
}

// ---------------- score / topk / compose / readout ----------------
__global__ void k_score(int n, const float* __restrict__ pw, int which) {
    int t = blockIdx.x * blockDim.x + threadIdx.x;
    int w = t >> 5, lane = t & 31;
    if (w >= n) return;
    float acc = 0.0f;
    for (int f = lane; f < H; f += 32) acc += g_h[w*H + f] * pw[f];
    #pragma unroll
    for (int s = 16; s > 0; s >>= 1) acc += __shfl_xor_sync(0xffffffffu, acc, s);
    if (lane == 0) g_score[w] = tanhf(acc / g_norm[which]);
}

// one block (512 thr) per graph: stable rank top-k; g_h -> g_hn (gated)
__global__ void k_topk(int n_per, int k) {
    int g = blockIdx.x;
    int tid = threadIdx.x;
    __shared__ float s[512];
    __shared__ int   rk[512];
    if (tid < n_per) s[tid] = g_score[g*n_per + tid];
    __syncthreads();
    if (tid < n_per) {
        float si = s[tid];
        int r = 0;
        for (int j = 0; j < n_per; j++) {
            float sj = s[j];
            r += (sj > si) || (sj == si && j < tid);
        }
        rk[tid] = r;
        g_inv[g*n_per + tid] = (r < k) ? (g*k + r) : -1;
    }
    __syncthreads();
    int tot = n_per * H;
    for (int idx = tid; idx < tot; idx += 512) {
        int node = idx >> 7;
        int f = idx & 127;
        int r = rk[node];
        if (r < k)
            g_hn[(g*k + r)*H + f] = g_h[(g*n_per + node)*H + f] * s[node];
    }
}

__global__ void k_compose() {
    int i = blockIdx.x * blockDim.x + threadIdx.x;
    if (i < NN) {
        int c = g_map[i];
        int nc = (c >= 0) ? g_inv[c] : -1;
        g_map[i] = nc;
        if (nc >= 0) g_perm[nc] = i;
    }
}

__global__ void k_readout(int k) {
    int g = blockIdx.x, f = threadIdx.x;  // 128 threads
    float mx = -INFINITY, sm = 0.0f;
    for (int r = 0; r < k; r++) {
        float v = g_hn[(g*k + r)*H + f];
        mx = fmaxf(mx, v);
        sm += v;
    }
    g_z[g*2*H + f]     += mx;
    g_z[g*2*H + H + f] += sm / (float)k;
}

// ---------------- MLP head ----------------
__global__ void k_fc1(const float* __restrict__ W, const float* __restrict__ b) {
    int r = blockIdx.x, o = threadIdx.x;   // 128 threads
    float acc = b[o];
    for (int f = 0; f < 2*H; f++) acc += g_z[r*2*H + f] * W[o*2*H + f];
    g_t1[r*H + o] = acc;
}
__global__ void k_fc2(const float* __restrict__ W, const float* __restrict__ b) {
    int r = blockIdx.x, o = threadIdx.x;   // 64 threads
    float acc = b[o];
    for (int f = 0; f < H; f++) acc += g_t1[r*H + f] * W[o*H + f];
    g_t2[r*64 + o] = acc;
}
__global__ void k_bn_relu(int sel, const float* __restrict__ gam,
                          const float* __restrict__ bet) {
    int F = sel ? 64 : H;
    float* Xp = sel ? g_t2 : g_t1;
    int f = blockIdx.x;
    int t = threadIdx.x;   // 64 threads
    __shared__ float sh[64];
    float s = 0.0f;
    for (int r = t; r < G; r += 64) s += Xp[r*F + f];
    sh[t] = s; __syncthreads();
    for (int st = 32; st > 0; st >>= 1) { if (t < st) sh[t] += sh[t + st]; __syncthreads(); }
    float mean = sh[0] / (float)G;
    __syncthreads();
    float v = 0.0f;
    for (int r = t; r < G; r += 64) { float d = Xp[r*F + f] - mean; v += d * d; }
    sh[t] = v; __syncthreads();
    for (int st = 32; st > 0; st >>= 1) { if (t < st) sh[t] += sh[t + st]; __syncthreads(); }
    float inv = 1.0f / sqrtf(sh[0] / (float)G + EPS);
    float gg = gam[f], bb = bet[f];
    for (int r = t; r < G; r += 64) {
        float y = (Xp[r*F + f] - mean) * inv * gg + bb;
        Xp[r*F + f] = fmaxf(y, 0.0f);
    }
}
__global__ void k_final(float* __restrict__ out,
                        const float* __restrict__ W,
                        const float* __restrict__ b) {
    int r = blockIdx.x * blockDim.x + threadIdx.x;
    if (r < G) {
        float l0 = b[0], l1 = b[1];
        for (int f = 0; f < 64; f++) {
            float v = g_t2[r*64 + f];
            l0 += v * W[f];
            l1 += v * W[64 + f];
        }
        float m = fmaxf(l0, l1);
        float e0 = expf(l0 - m), e1 = expf(l1 - m);
        float s = e0 + e1;
        out[r*2]     = e0 / s;
        out[r*2 + 1] = e1 / s;
    }
}

// ---------------- launch sequence ----------------
extern "C" void kernel_launch(void* const* d_in, const int* in_sizes, int n_in,
                              void* d_out, int out_size) {
    const float* x      = (const float*)d_in[0];
    const int*   ei     = (const int*)  d_in[1];
    const float* Wrel1  = (const float*)d_in[2];
    const float* Wroot1 = (const float*)d_in[3];
    const float* b1     = (const float*)d_in[4];
    const float* Wrel2  = (const float*)d_in[5];
    const float* Wroot2 = (const float*)d_in[6];
    const float* b2     = (const float*)d_in[7];
    const float* Wrel3  = (const float*)d_in[8];
    const float* Wroot3 = (const float*)d_in[9];
    const float* b3     = (const float*)d_in[10];
    const float* pw1    = (const float*)d_in[11];
    const float* pw2    = (const float*)d_in[12];
    const float* pw3    = (const float*)d_in[13];
    const float* lin1_w = (const float*)d_in[14];
    const float* lin1_b = (const float*)d_in[15];
    const float* lin2_w = (const float*)d_in[16];
    const float* lin2_b = (const float*)d_in[17];
    const float* lin3_w = (const float*)d_in[18];
    const float* lin3_b = (const float*)d_in[19];
    const float* bn1_g  = (const float*)d_in[20];
    const float* bn1_b  = (const float*)d_in[21];
    const float* bn2_g  = (const float*)d_in[22];
    const float* bn2_b  = (const float*)d_in[23];
    float* out = (float*)d_out;

    int* cntp;   cudaGetSymbolAddress((void**)&cntp, g_csr_cnt);
    float* aggp; cudaGetSymbolAddress((void**)&aggp, g_agg);
    float* zp;   cudaGetSymbolAddress((void**)&zp, g_z);

    // CSR build + init
    k_zero_int<<<(NN + 255)/256, 256>>>(cntp, NN);
    k_zero_f<<<(G*2*H + 255)/256, 256>>>(zp, G*2*H);
    k_hist<<<(ET + 255)/256, 256>>>(ei);
    k_scan1<<<100, 1024>>>();
    k_scan2<<<1, 1>>>();
    k_scan3<<<100, 1024>>>();
    k_fill<<<(ET + 255)/256, 256>>>(ei);
    k_initmaps<<<(NN + 255)/256, 256>>>();
    k_norms<<<1, 128>>>(pw1, pw2, pw3);

    // ----- level 1 -----
    k_zero_f<<<(NN*FIN + 255)/256, 256>>>(aggp, NN*FIN);
    k_scatter6<<<(ET + 255)/256, 256>>>(x, ei);
    k_conv1<<<NN/4, 512>>>(x, Wrel1, Wroot1, b1);
    k_score<<<(NN*32 + 255)/256, 256>>>(NN, pw1, 0);
    k_topk<<<G, 512>>>(N0, K1);
    k_compose<<<(NN + 255)/256, 256>>>();
    k_readout<<<G, H>>>(K1);

    // ----- level 2 -----
    const int n2 = G * K1;
    k_gather<<<n2, H>>>();
    k_convH<<<(n2 + 63)/64, 256>>>(n2, Wrel2, Wroot2, b2);
    k_score<<<(n2*32 + 255)/256, 256>>>(n2, pw2, 1);
    k_topk<<<G, 512>>>(K1, K2);
    k_compose<<<(NN + 255)/256, 256>>>();
    k_readout<<<G, H>>>(K2);

    // ----- level 3 -----
    const int n3 = G * K2;
    k_gather<<<n3, H>>>();
    k_convH<<<(n3 + 63)/64, 256>>>(n3, Wrel3, Wroot3, b3);
    k_score<<<(n3*32 + 255)/256, 256>>>(n3, pw3, 2);
    k_topk<<<G, 512>>>(K2, K3);
    k_readout<<<G, H>>>(K3);

    // ----- MLP head -----
    k_fc1<<<G, H>>>(lin1_w, lin1_b);
    k_bn_relu<<<H, 64>>>(0, bn1_g, bn1_b);
    k_fc2<<<G, 64>>>(lin2_w, lin2_b);
    k_bn_relu<<<64, 64>>>(1, bn2_g, bn2_b);
    k_final<<<(G + 127)/128, 128>>>(out, lin3_w, lin3_b);
}

// round 3
// speedup vs baseline: 1.6558x; 1.0327x over previous
#include <cuda_runtime.h>
#include <math.h>

#define G      200
#define N0     512
#define NN     (G*N0)        // 102400
#define DEG    6
#define ET     (G*N0*DEG)    // 614400
#define K1     410
#define K2     328
#define K3     263
#define FIN    6
#define H      128
#define EPS    1e-5f

typedef unsigned long long u64;

// ---------------- device scratch ----------------
__device__ float g_h  [NN*H];     // conv outputs (pre-pool)
__device__ float g_hn [NN*H];     // pooled features
__device__ float g_agg[NN*H];     // neighbor aggregation (levels 2,3)
__device__ float g_score[NN];
__device__ int   g_map[NN];       // orig node -> current id (or -1)
__device__ int   g_perm[NN];      // current id -> orig node
__device__ int   g_csr_off[NN+1];
__device__ int   g_csr_cnt[NN];
__device__ int   g_cur[NN];
__device__ int   g_csr_src[ET];
__device__ int   g_bsum[128];
__device__ float g_z[G*2*H];
__device__ float g_t1[G*H];
__device__ float g_t2[G*64];
__device__ float g_norm[3];

// ---------------- f32x2 helpers ----------------
__device__ __forceinline__ u64 pack2(float x, float y) {
    u64 r; asm("mov.b64 %0,{%1,%2};" : "=l"(r) : "f"(x), "f"(y)); return r;
}
__device__ __forceinline__ u64 fma2(u64 a, u64 b, u64 c) {
    u64 d; asm("fma.rn.f32x2 %0,%1,%2,%3;" : "=l"(d) : "l"(a), "l"(b), "l"(c)); return d;
}
__device__ __forceinline__ float2 unpack2(u64 v) {
    float2 f; asm("mov.b64 {%0,%1},%2;" : "=f"(f.x), "=f"(f.y) : "l"(v)); return f;
}

// ---------------- init: zero cnt, ident maps, pw norms ----------------
__global__ void k_init(const float* __restrict__ pw1,
                       const float* __restrict__ pw2,
                       const float* __restrict__ pw3) {
    int i = blockIdx.x * blockDim.x + threadIdx.x;
    if (i < NN) { g_csr_cnt[i] = 0; g_map[i] = i; g_perm[i] = i; }
    if (blockIdx.x == 0) {
        __shared__ float sh[256];
        int t = threadIdx.x;
        const float* pws[3] = {pw1, pw2, pw3};
        #pragma unroll
        for (int j = 0; j < 3; j++) {
            float v = (t < H) ? pws[j][t] : 0.0f;
            sh[t] = v * v;
            __syncthreads();
            for (int s = 128; s > 0; s >>= 1) {
                if (t < s) sh[t] += sh[t + s];
                __syncthreads();
            }
            if (t == 0) g_norm[j] = sqrtf(sh[0]);
            __syncthreads();
        }
    }
}

// ---------------- CSR build ----------------
__global__ void k_hist(const int* __restrict__ ei) {
    int e = blockIdx.x * blockDim.x + threadIdx.x;
    if (e < ET) atomicAdd(&g_csr_cnt[ei[ET + e]], 1);
}
__global__ void k_scan1() {   // 100 blocks x 1024
    __shared__ int sh[1024];
    int tid = threadIdx.x;
    int gid = blockIdx.x * 1024 + tid;
    int v = g_csr_cnt[gid];
    sh[tid] = v;
    __syncthreads();
    for (int off = 1; off < 1024; off <<= 1) {
        int t = (tid >= off) ? sh[tid - off] : 0;
        __syncthreads();
        sh[tid] += t;
        __syncthreads();
    }
    g_csr_off[gid] = sh[tid] - v;              // exclusive within block
    if (tid == 1023) g_bsum[blockIdx.x] = sh[tid];
}
__global__ void k_scan3() {   // 100 blocks x 1024 (block-prefix computed inline)
    __shared__ int base;
    if (threadIdx.x == 0) {
        int run = 0;
        for (int b = 0; b < blockIdx.x; b++) run += g_bsum[b];
        base = run;
        if (blockIdx.x == 0) g_csr_off[NN] = ET;
    }
    __syncthreads();
    int gid = blockIdx.x * 1024 + threadIdx.x;
    int v = g_csr_off[gid] + base;
    g_csr_off[gid] = v;
    g_cur[gid] = v;
}
__global__ void k_fill(const int* __restrict__ ei) {
    int e = blockIdx.x * blockDim.x + threadIdx.x;
    if (e < ET) {
        int idx = atomicAdd(&g_cur[ei[ET + e]], 1);
        g_csr_src[idx] = ei[e];
    }
}

// ---------------- level 1: gather + conv(F_IN=6) + score, fused ----------------
__global__ void k_conv1f(const float* __restrict__ x,
                         const float* __restrict__ Wrel,
                         const float* __restrict__ Wroot,
                         const float* __restrict__ b,
                         const float* __restrict__ pw) {
    int node = blockIdx.x;
    int o = threadIdx.x;           // 128 threads
    __shared__ float sx[FIN], sa[FIN], sred[4];
    if (o < FIN) {
        sx[o] = x[node*FIN + o];
        int s0 = g_csr_off[node], s1 = g_csr_off[node + 1];
        float acc = 0.0f;
        for (int i = s0; i < s1; i++) acc += x[g_csr_src[i]*FIN + o];
        sa[o] = acc;
    }
    __syncthreads();
    float acc = b[o];
    #pragma unroll
    for (int f = 0; f < FIN; f++)
        acc += sa[f] * Wrel[o*FIN + f] + sx[f] * Wroot[o*FIN + f];
    float h = fmaxf(acc, 0.0f);
    g_h[node*H + o] = h;
    // score: dot(h, pw)
    float p = h * pw[o];
    #pragma unroll
    for (int s = 16; s > 0; s >>= 1) p += __shfl_xor_sync(0xffffffffu, p, s);
    if ((o & 31) == 0) sred[o >> 5] = p;
    __syncthreads();
    if (o == 0)
        g_score[node] = tanhf((sred[0] + sred[1] + sred[2] + sred[3]) / g_norm[0]);
}

// ---------------- H=128 conv (f32x2) + fused score ----------------
// Y = relu( X@Wroot^T + AGG@Wrel^T + b ); X = g_hn, Y = g_h; score -> g_score
__global__ void k_convH(int n,
                        const float* __restrict__ Wrel,
                        const float* __restrict__ Wroot,
                        const float* __restrict__ b,
                        const float* __restrict__ pw, int which) {
    const float* X = g_hn;
    float* Y = g_h;
    __shared__ __align__(16) u64   sA[16][66];
    __shared__ __align__(16) float sB[16][132];
    int m0  = blockIdx.x * 64;
    int tid = threadIdx.x;
    int tm  = (tid >> 5) * 8;       // node offset (warp-uniform)
    int tn  = (tid & 31) * 4;       // out offset
    u64 acc[8][2];
    #pragma unroll
    for (int i = 0; i < 8; i++) { acc[i][0] = 0ULL; acc[i][1] = 0ULL; }

    for (int kt = 0; kt < 256; kt += 16) {
        #pragma unroll
        for (int l = 0; l < 4; l++) {
            int idx = tid + l * 256;
            int mm = idx >> 4, kk = idx & 15;
            int k = kt + kk;
            int node = m0 + mm;
            float v = 0.0f;
            if (node < n)
                v = (k < 128) ? X[node*H + k] : g_agg[node*H + (k - 128)];
            sA[kk][mm] = pack2(v, v);
        }
        #pragma unroll
        for (int l = 0; l < 8; l++) {
            int idx = tid + l * 256;
            int oo = idx >> 4, kk = idx & 15;
            int k = kt + kk;
            sB[kk][oo] = (k < 128) ? Wroot[oo*H + k] : Wrel[oo*H + (k - 128)];
        }
        __syncthreads();
        #pragma unroll
        for (int kk = 0; kk < 16; kk++) {
            ulonglong2 p0 = *(const ulonglong2*)&sA[kk][tm];
            ulonglong2 p1 = *(const ulonglong2*)&sA[kk][tm + 2];
            ulonglong2 p2 = *(const ulonglong2*)&sA[kk][tm + 4];
            ulonglong2 p3 = *(const ulonglong2*)&sA[kk][tm + 6];
            float4 bb = *(const float4*)&sB[kk][tn];
            u64 b01 = pack2(bb.x, bb.y);
            u64 b23 = pack2(bb.z, bb.w);
            u64 av[8] = {p0.x, p0.y, p1.x, p1.y, p2.x, p2.y, p3.x, p3.y};
            #pragma unroll
            for (int i = 0; i < 8; i++) {
                acc[i][0] = fma2(av[i], b01, acc[i][0]);
                acc[i][1] = fma2(av[i], b23, acc[i][1]);
            }
        }
        __syncthreads();
    }
    float4 bb4 = *(const float4*)&b[tn];
    float4 pwv = *(const float4*)&pw[tn];
    float nrm = g_norm[which];
    #pragma unroll
    for (int i = 0; i < 8; i++) {
        int node = m0 + tm + i;
        float2 v0 = unpack2(acc[i][0]);
        float2 v1 = unpack2(acc[i][1]);
        float4 o;
        o.x = fmaxf(v0.x + bb4.x, 0.0f);
        o.y = fmaxf(v0.y + bb4.y, 0.0f);
        o.z = fmaxf(v1.x + bb4.z, 0.0f);
        o.w = fmaxf(v1.y + bb4.w, 0.0f);
        float p = o.x*pwv.x + o.y*pwv.y + o.z*pwv.z + o.w*pwv.w;
        #pragma unroll
        for (int s = 16; s > 0; s >>= 1) p += __shfl_xor_sync(0xffffffffu, p, s);
        if (node < n) {
            *(float4*)&Y[node*H + tn] = o;
            if ((tid & 31) == 0) g_score[node] = tanhf(p / nrm);
        }
    }
}

// ---------------- fused pool: rank + gate + compose + readout + next-gather ----
// one block (512 thr) per graph
__global__ void k_pool(int n_per, int k, int store_z, int do_gather) {
    int g = blockIdx.x;
    int tid = threadIdx.x;
    __shared__ float s[512];
    __shared__ int   rk[512];
    __shared__ float red1[512];
    if (tid < n_per) s[tid] = g_score[g*n_per + tid];
    __syncthreads();
    int myrank = 0x7fffffff;
    if (tid < n_per) {
        float si = s[tid];
        int r = 0;
        for (int j = 0; j < n_per; j++) {
            float sj = s[j];
            r += (sj > si) || (sj == si && j < tid);
        }
        rk[tid] = r;
        myrank = r;
    }
    __syncthreads();
    // gated copy g_h -> g_hn at new ids
    int tot = n_per * H;
    for (int idx = tid; idx < tot; idx += 512) {
        int node = idx >> 7;
        int f = idx & 127;
        int r = rk[node];
        if (r < k)
            g_hn[(g*k + r)*H + f] = g_h[(g*n_per + node)*H + f] * s[node];
    }
    // compose orig->current map (this graph's 512 orig nodes)
    {
        int orig = g*N0 + tid;
        int c = g_map[orig];
        int nc = -1;
        if (c >= 0) {
            int r = rk[c - g*n_per];
            nc = (r < k) ? (g*k + r) : -1;
        }
        g_map[orig] = nc;
        if (nc >= 0) g_perm[nc] = orig;
    }
    __syncthreads();   // g_hn + maps visible block-wide
    // readout: max then mean over k nodes, 128 feats
    {
        int f = tid & 127, part = tid >> 7;   // 4 parts
        float mx = -INFINITY, sm = 0.0f;
        for (int r = part; r < k; r += 4) {
            float v = g_hn[(g*k + r)*H + f];
            mx = fmaxf(mx, v);
            sm += v;
        }
        red1[tid] = mx;
        __syncthreads();
        if (part == 0) {
            float m = fmaxf(fmaxf(red1[f], red1[128 + f]),
                            fmaxf(red1[256 + f], red1[384 + f]));
            if (store_z) g_z[g*2*H + f] = m;
            else         g_z[g*2*H + f] += m;
        }
        __syncthreads();
        red1[tid] = sm;
        __syncthreads();
        if (part == 0) {
            float m = red1[f] + red1[128 + f] + red1[256 + f] + red1[384 + f];
            m /= (float)k;
            if (store_z) g_z[g*2*H + H + f] = m;
            else         g_z[g*2*H + H + f] += m;
        }
    }
    // gather for next level: agg[new id] = sum over orig-CSR neighbors still alive
    if (do_gather) {
        __syncthreads();
        int totk = k * H;
        for (int idx = tid; idx < totk; idx += 512) {
            int r = idx >> 7;       // new local id
            int f = idx & 127;
            int orig = g_perm[g*k + r];
            int s0 = g_csr_off[orig], s1 = g_csr_off[orig + 1];
            float acc = 0.0f;
            for (int i = s0; i < s1; i++) {
                int m = g_map[g_csr_src[i]];
                if (m >= 0) acc += g_hn[m*H + f];
            }
            g_agg[(g*k + r)*H + f] = acc;
        }
    }
}

// ---------------- MLP head ----------------
__global__ void k_fc1(const float* __restrict__ W, const float* __restrict__ b) {
    int r = blockIdx.x, o = threadIdx.x;   // 128 threads
    float acc = b[o];
    for (int f = 0; f < 2*H; f++) acc += g_z[r*2*H + f] * W[o*2*H + f];
    g_t1[r*H + o] = acc;
}
__global__ void k_fc2(const float* __restrict__ W, const float* __restrict__ b) {
    int r = blockIdx.x, o = threadIdx.x;   // 64 threads
    float acc = b[o];
    for (int f = 0; f < H; f++) acc += g_t1[r*H + f] * W[o*H + f];
    g_t2[r*64 + o] = acc;
}
__global__ void k_bn_relu(int sel, const float* __restrict__ gam,
                          const float* __restrict__ bet) {
    int F = sel ? 64 : H;
    float* Xp = sel ? g_t2 : g_t1;
    int f = blockIdx.x;
    int t = threadIdx.x;   // 64 threads
    __shared__ float sh[64];
    float s = 0.0f;
    for (int r = t; r < G; r += 64) s += Xp[r*F + f];
    sh[t] = s; __syncthreads();
    for (int st = 32; st > 0; st >>= 1) { if (t < st) sh[t] += sh[t + st]; __syncthreads(); }
    float mean = sh[0] / (float)G;
    __syncthreads();
    float v = 0.0f;
    for (int r = t; r < G; r += 64) { float d = Xp[r*F + f] - mean; v += d * d; }
    sh[t] = v; __syncthreads();
    for (int st = 32; st > 0; st >>= 1) { if (t < st) sh[t] += sh[t + st]; __syncthreads(); }
    float inv = 1.0f / sqrtf(sh[0] / (float)G + EPS);
    float gg = gam[f], bb = bet[f];
    for (int r = t; r < G; r += 64) {
        float y = (Xp[r*F + f] - mean) * inv * gg + bb;
        Xp[r*F + f] = fmaxf(y, 0.0f);
    }
}
__global__ void k_final(float* __restrict__ out,
                        const float* __restrict__ W,
                        const float* __restrict__ b) {
    int r = blockIdx.x * blockDim.x + threadIdx.x;
    if (r < G) {
        float l0 = b[0], l1 = b[1];
        for (int f = 0; f < 64; f++) {
            float v = g_t2[r*64 + f];
            l0 += v * W[f];
            l1 += v * W[64 + f];
        }
        float m = fmaxf(l0, l1);
        float e0 = expf(l0 - m), e1 = expf(l1 - m);
        float sum = e0 + e1;
        out[r*2]     = e0 / sum;
        out[r*2 + 1] = e1 / sum;
    }
}

// ---------------- launch sequence (16 launches) ----------------
extern "C" void kernel_launch(void* const* d_in, const int* in_sizes, int n_in,
                              void* d_out, int out_size) {
    const float* x      = (const float*)d_in[0];
    const int*   ei     = (const int*)  d_in[1];
    const float* Wrel1  = (const float*)d_in[2];
    const float* Wroot1 = (const float*)d_in[3];
    const float* b1     = (const float*)d_in[4];
    const float* Wrel2  = (const float*)d_in[5];
    const float* Wroot2 = (const float*)d_in[6];
    const float* b2     = (const float*)d_in[7];
    const float* Wrel3  = (const float*)d_in[8];
    const float* Wroot3 = (const float*)d_in[9];
    const float* b3     = (const float*)d_in[10];
    const float* pw1    = (const float*)d_in[11];
    const float* pw2    = (const float*)d_in[12];
    const float* pw3    = (const float*)d_in[13];
    const float* lin1_w = (const float*)d_in[14];
    const float* lin1_b = (const float*)d_in[15];
    const float* lin2_w = (const float*)d_in[16];
    const float* lin2_b = (const float*)d_in[17];
    const float* lin3_w = (const float*)d_in[18];
    const float* lin3_b = (const float*)d_in[19];
    const float* bn1_g  = (const float*)d_in[20];
    const float* bn1_b  = (const float*)d_in[21];
    const float* bn2_g  = (const float*)d_in[22];
    const float* bn2_b  = (const float*)d_in[23];
    float* out = (float*)d_out;

    // CSR build + init
    k_init<<<(NN + 255)/256, 256>>>(pw1, pw2, pw3);
    k_hist<<<(ET + 255)/256, 256>>>(ei);
    k_scan1<<<100, 1024>>>();
    k_scan3<<<100, 1024>>>();
    k_fill<<<(ET + 255)/256, 256>>>(ei);

    // level 1
    k_conv1f<<<NN, H>>>(x, Wrel1, Wroot1, b1, pw1);
    k_pool<<<G, 512>>>(N0, K1, 1, 1);
    // level 2
    const int n2 = G * K1;
    k_convH<<<(n2 + 63)/64, 256>>>(n2, Wrel2, Wroot2, b2, pw2, 1);
    k_pool<<<G, 512>>>(K1, K2, 0, 1);
    // level 3
    const int n3 = G * K2;
    k_convH<<<(n3 + 63)/64, 256>>>(n3, Wrel3, Wroot3, b3, pw3, 2);
    k_pool<<<G, 512>>>(K2, K3, 0, 0);

    // MLP head
    k_fc1<<<G, H>>>(lin1_w, lin1_b);
    k_bn_relu<<<H, 64>>>(0, bn1_g, bn1_b);
    k_fc2<<<G, 64>>>(lin2_w, lin2_b);
    k_bn_relu<<<64, 64>>>(1, bn2_g, bn2_b);
    k_final<<<(G + 127)/128, 128>>>(out, lin3_w, lin3_b);
}

// round 4
// speedup vs baseline: 1.7525x; 1.0584x over previous
#include <cuda_runtime.h>
#include <math.h>

#define G      200
#define N0     512
#define NN     (G*N0)        // 102400
#define DEG    6
#define ET     (G*N0*DEG)    // 614400
#define K1     410
#define K2     328
#define K3     263
#define FIN    6
#define H      128
#define EPS    1e-5f

typedef unsigned long long u64;

// ---------------- device scratch ----------------
__device__ float g_h  [NN*H];     // conv outputs (pre-pool)
__device__ float g_hn [NN*H];     // pooled features
__device__ float g_agg[NN*H];     // neighbor aggregation (levels 2,3)
__device__ float g_score[NN];
__device__ int   g_map[NN];       // orig node -> current id (or -1)
__device__ int   g_perm[NN];      // current id -> orig node
__device__ int   g_sel[NN];       // new id -> old local id (within graph)
__device__ float g_gs[NN];        // new id -> gate scale (score)
__device__ int   g_csr_off[NN+1];
__device__ int   g_csr_cnt[NN];
__device__ int   g_cur[NN];
__device__ int   g_csr_src[ET];
__device__ int   g_bsum[128];
__device__ float g_z[G*2*H];
__device__ float g_t1[G*H];
__device__ float g_t2[G*64];
__device__ float g_norm[3];

// ---------------- f32x2 helpers ----------------
__device__ __forceinline__ u64 pack2(float x, float y) {
    u64 r; asm("mov.b64 %0,{%1,%2};" : "=l"(r) : "f"(x), "f"(y)); return r;
}
__device__ __forceinline__ u64 fma2(u64 a, u64 b, u64 c) {
    u64 d; asm("fma.rn.f32x2 %0,%1,%2,%3;" : "=l"(d) : "l"(a), "l"(b), "l"(c)); return d;
}
__device__ __forceinline__ float2 unpack2(u64 v) {
    float2 f; asm("mov.b64 {%0,%1},%2;" : "=f"(f.x), "=f"(f.y) : "l"(v)); return f;
}

// ---------------- init: zero cnt, ident maps, pw norms ----------------
__global__ void k_init(const float* __restrict__ pw1,
                       const float* __restrict__ pw2,
                       const float* __restrict__ pw3) {
    int i = blockIdx.x * blockDim.x + threadIdx.x;
    if (i < NN) { g_csr_cnt[i] = 0; g_map[i] = i; g_perm[i] = i; }
    if (blockIdx.x == 0) {
        __shared__ float sh[256];
        int t = threadIdx.x;
        const float* pws[3] = {pw1, pw2, pw3};
        #pragma unroll
        for (int j = 0; j < 3; j++) {
            float v = (t < H) ? pws[j][t] : 0.0f;
            sh[t] = v * v;
            __syncthreads();
            for (int s = 128; s > 0; s >>= 1) {
                if (t < s) sh[t] += sh[t + s];
                __syncthreads();
            }
            if (t == 0) g_norm[j] = sqrtf(sh[0]);
            __syncthreads();
        }
    }
}

// ---------------- CSR build ----------------
__global__ void k_hist(const int* __restrict__ ei) {
    int e = blockIdx.x * blockDim.x + threadIdx.x;
    if (e < ET) atomicAdd(&g_csr_cnt[ei[ET + e]], 1);
}
__global__ void k_scan1() {   // 100 blocks x 1024
    __shared__ int sh[1024];
    int tid = threadIdx.x;
    int gid = blockIdx.x * 1024 + tid;
    int v = g_csr_cnt[gid];
    sh[tid] = v;
    __syncthreads();
    for (int off = 1; off < 1024; off <<= 1) {
        int t = (tid >= off) ? sh[tid - off] : 0;
        __syncthreads();
        sh[tid] += t;
        __syncthreads();
    }
    g_csr_off[gid] = sh[tid] - v;              // exclusive within block
    if (tid == 1023) g_bsum[blockIdx.x] = sh[tid];
}
__global__ void k_scan3() {   // 100 blocks x 1024; parallel bsum scan
    __shared__ int sb[128];
    int tid = threadIdx.x;
    if (tid < 128) sb[tid] = (tid < 100) ? g_bsum[tid] : 0;
    __syncthreads();
    for (int off = 1; off < 128; off <<= 1) {
        int v = (tid < 128 && tid >= off) ? sb[tid - off] : 0;
        __syncthreads();
        if (tid < 128) sb[tid] += v;
        __syncthreads();
    }
    int base = (blockIdx.x == 0) ? 0 : sb[blockIdx.x - 1];
    if (blockIdx.x == 0 && tid == 0) g_csr_off[NN] = ET;
    int gid = blockIdx.x * 1024 + tid;
    int v = g_csr_off[gid] + base;
    g_csr_off[gid] = v;
    g_cur[gid] = v;
}
__global__ void k_fill(const int* __restrict__ ei) {
    int e = blockIdx.x * blockDim.x + threadIdx.x;
    if (e < ET) {
        int idx = atomicAdd(&g_cur[ei[ET + e]], 1);
        g_csr_src[idx] = ei[e];
    }
}

// ---------------- level 1: gather + conv(F_IN=6) + score, fused ----------------
__global__ void k_conv1f(const float* __restrict__ x,
                         const float* __restrict__ Wrel,
                         const float* __restrict__ Wroot,
                         const float* __restrict__ b,
                         const float* __restrict__ pw) {
    int node = blockIdx.x;
    int o = threadIdx.x;           // 128 threads
    __shared__ float sx[FIN], sa[FIN], sred[4];
    if (o < FIN) {
        sx[o] = x[node*FIN + o];
        int s0 = g_csr_off[node], s1 = g_csr_off[node + 1];
        float acc = 0.0f;
        for (int i = s0; i < s1; i++) acc += x[g_csr_src[i]*FIN + o];
        sa[o] = acc;
    }
    __syncthreads();
    float acc = b[o];
    #pragma unroll
    for (int f = 0; f < FIN; f++)
        acc += sa[f] * Wrel[o*FIN + f] + sx[f] * Wroot[o*FIN + f];
    float h = fmaxf(acc, 0.0f);
    g_h[node*H + o] = h;
    float p = h * pw[o];
    #pragma unroll
    for (int s = 16; s > 0; s >>= 1) p += __shfl_xor_sync(0xffffffffu, p, s);
    if ((o & 31) == 0) sred[o >> 5] = p;
    __syncthreads();
    if (o == 0)
        g_score[node] = tanhf((sred[0] + sred[1] + sred[2] + sred[3]) / g_norm[0]);
}

// ---------------- H=128 conv (f32x2) + fused score ----------------
__global__ void k_convH(int n,
                        const float* __restrict__ Wrel,
                        const float* __restrict__ Wroot,
                        const float* __restrict__ b,
                        const float* __restrict__ pw, int which) {
    const float* X = g_hn;
    float* Y = g_h;
    __shared__ __align__(16) u64   sA[16][66];
    __shared__ __align__(16) float sB[16][132];
    int m0  = blockIdx.x * 64;
    int tid = threadIdx.x;
    int tm  = (tid >> 5) * 8;
    int tn  = (tid & 31) * 4;
    u64 acc[8][2];
    #pragma unroll
    for (int i = 0; i < 8; i++) { acc[i][0] = 0ULL; acc[i][1] = 0ULL; }

    for (int kt = 0; kt < 256; kt += 16) {
        #pragma unroll
        for (int l = 0; l < 4; l++) {
            int idx = tid + l * 256;
            int mm = idx >> 4, kk = idx & 15;
            int k = kt + kk;
            int node = m0 + mm;
            float v = 0.0f;
            if (node < n)
                v = (k < 128) ? X[node*H + k] : g_agg[node*H + (k - 128)];
            sA[kk][mm] = pack2(v, v);
        }
        #pragma unroll
        for (int l = 0; l < 8; l++) {
            int idx = tid + l * 256;
            int oo = idx >> 4, kk = idx & 15;
            int k = kt + kk;
            sB[kk][oo] = (k < 128) ? Wroot[oo*H + k] : Wrel[oo*H + (k - 128)];
        }
        __syncthreads();
        #pragma unroll
        for (int kk = 0; kk < 16; kk++) {
            ulonglong2 p0 = *(const ulonglong2*)&sA[kk][tm];
            ulonglong2 p1 = *(const ulonglong2*)&sA[kk][tm + 2];
            ulonglong2 p2 = *(const ulonglong2*)&sA[kk][tm + 4];
            ulonglong2 p3 = *(const ulonglong2*)&sA[kk][tm + 6];
            float4 bb = *(const float4*)&sB[kk][tn];
            u64 b01 = pack2(bb.x, bb.y);
            u64 b23 = pack2(bb.z, bb.w);
            u64 av[8] = {p0.x, p0.y, p1.x, p1.y, p2.x, p2.y, p3.x, p3.y};
            #pragma unroll
            for (int i = 0; i < 8; i++) {
                acc[i][0] = fma2(av[i], b01, acc[i][0]);
                acc[i][1] = fma2(av[i], b23, acc[i][1]);
            }
        }
        __syncthreads();
    }
    float4 bb4 = *(const float4*)&b[tn];
    float4 pwv = *(const float4*)&pw[tn];
    float nrm = g_norm[which];
    #pragma unroll
    for (int i = 0; i < 8; i++) {
        int node = m0 + tm + i;
        float2 v0 = unpack2(acc[i][0]);
        float2 v1 = unpack2(acc[i][1]);
        float4 o;
        o.x = fmaxf(v0.x + bb4.x, 0.0f);
        o.y = fmaxf(v0.y + bb4.y, 0.0f);
        o.z = fmaxf(v1.x + bb4.z, 0.0f);
        o.w = fmaxf(v1.y + bb4.w, 0.0f);
        float p = o.x*pwv.x + o.y*pwv.y + o.z*pwv.z + o.w*pwv.w;
        #pragma unroll
        for (int s = 16; s > 0; s >>= 1) p += __shfl_xor_sync(0xffffffffu, p, s);
        if (node < n) {
            *(float4*)&Y[node*H + tn] = o;
            if ((tid & 31) == 0) g_score[node] = tanhf(p / nrm);
        }
    }
}

// ---------------- rank: per-graph stable top-k ranks + compose + sel ----------
__global__ void k_rank(int n_per, int k) {
    int g = blockIdx.x;
    int tid = threadIdx.x;   // 512
    __shared__ float s[512];
    __shared__ int   rk[512];
    if (tid < n_per) s[tid] = g_score[g*n_per + tid];
    __syncthreads();
    if (tid < n_per) {
        float si = s[tid];
        int r = 0;
        for (int j = 0; j < n_per; j++) {
            float sj = s[j];
            r += (sj > si) || (sj == si && j < tid);
        }
        rk[tid] = r;
        if (r < k) { g_sel[g*k + r] = tid; g_gs[g*k + r] = si; }
    }
    __syncthreads();
    // compose orig->current map (this graph's 512 orig nodes)
    int orig = g*N0 + tid;
    int c = g_map[orig];
    int nc = -1;
    if (c >= 0) {
        int r = rk[c - g*n_per];
        nc = (r < k) ? (g*k + r) : -1;
    }
    g_map[orig] = nc;
    if (nc >= 0) g_perm[nc] = orig;
}

// ---------------- gated copy: one block (128 thr) per kept node ---------------
__global__ void k_copy(int n_per, int k) {
    int j = blockIdx.x;              // new global id
    int f = threadIdx.x;
    int g = j / k;
    int old = g * n_per + g_sel[j];
    g_hn[j*H + f] = g_h[old*H + f] * g_gs[j];
}

// ---------------- readout: per-graph max+mean over k nodes --------------------
__global__ void k_readout(int k, int store_z) {
    int g = blockIdx.x;
    int tid = threadIdx.x;           // 512
    __shared__ float red[512];
    int f = tid & 127, part = tid >> 7;
    float mx = -INFINITY, sm = 0.0f;
    for (int r = part; r < k; r += 4) {
        float v = g_hn[(g*k + r)*H + f];
        mx = fmaxf(mx, v);
        sm += v;
    }
    red[tid] = mx;
    __syncthreads();
    if (part == 0) {
        float m = fmaxf(fmaxf(red[f], red[128 + f]), fmaxf(red[256 + f], red[384 + f]));
        if (store_z) g_z[g*2*H + f] = m;
        else         g_z[g*2*H + f] += m;
    }
    __syncthreads();
    red[tid] = sm;
    __syncthreads();
    if (part == 0) {
        float m = (red[f] + red[128 + f] + red[256 + f] + red[384 + f]) / (float)k;
        if (store_z) g_z[g*2*H + H + f] = m;
        else         g_z[g*2*H + H + f] += m;
    }
}

// ---------------- gather: one block (128 thr) per kept node -------------------
__global__ void k_gather() {
    int v = blockIdx.x;
    int f = threadIdx.x;
    int u = g_perm[v];
    int start = g_csr_off[u], end = g_csr_off[u + 1];
    int deg = end - start;
    __shared__ int sw[64];
    int m = deg < 64 ? deg : 64;
    if (f < m) sw[f] = g_map[g_csr_src[start + f]];
    __syncthreads();
    float acc = 0.0f;
    for (int i = 0; i < m; i++) {
        int w = sw[i];
        if (w >= 0) acc += g_hn[w*H + f];
    }
    for (int i = 64; i < deg; i++) {
        int w = g_map[g_csr_src[start + i]];
        if (w >= 0) acc += g_hn[w*H + f];
    }
    g_agg[v*H + f] = acc;
}

// ---------------- MLP head (coalesced warp-per-out) ----------------
// fc1: t1[r][o] = b[o] + dot(z[r], W[o]), F=256. grid (16,50), 256 thr.
__global__ void k_fc1(const float* __restrict__ W, const float* __restrict__ b) {
    int w = threadIdx.x >> 5, lane = threadIdx.x & 31;
    int o = blockIdx.x * 8 + w;
    int r0 = blockIdx.y * 4;
    const float* Wo = &W[o*2*H];
    float wreg[8];
    #pragma unroll
    for (int i = 0; i < 8; i++) wreg[i] = Wo[lane + 32*i];
    #pragma unroll
    for (int rr = 0; rr < 4; rr++) {
        int r = r0 + rr;
        const float* zr = &g_z[r*2*H];
        float acc = 0.0f;
        #pragma unroll
        for (int i = 0; i < 8; i++) acc += zr[lane + 32*i] * wreg[i];
        #pragma unroll
        for (int s = 16; s > 0; s >>= 1) acc += __shfl_xor_sync(0xffffffffu, acc, s);
        if (lane == 0) g_t1[r*H + o] = acc + b[o];
    }
}
// fc2: t2[r][o] = b[o] + dot(t1[r], W[o]), F=128. grid (8,25), 256 thr.
__global__ void k_fc2(const float* __restrict__ W, const float* __restrict__ b) {
    int w = threadIdx.x >> 5, lane = threadIdx.x & 31;
    int o = blockIdx.x * 8 + w;
    int r0 = blockIdx.y * 8;
    const float* Wo = &W[o*H];
    float wreg[4];
    #pragma unroll
    for (int i = 0; i < 4; i++) wreg[i] = Wo[lane + 32*i];
    #pragma unroll
    for (int rr = 0; rr < 8; rr++) {
        int r = r0 + rr;
        const float* tr = &g_t1[r*H];
        float acc = 0.0f;
        #pragma unroll
        for (int i = 0; i < 4; i++) acc += tr[lane + 32*i] * wreg[i];
        #pragma unroll
        for (int s = 16; s > 0; s >>= 1) acc += __shfl_xor_sync(0xffffffffu, acc, s);
        if (lane == 0) g_t2[r*64 + o] = acc + b[o];
    }
}
__global__ void k_bn_relu(int sel, const float* __restrict__ gam,
                          const float* __restrict__ bet) {
    int F = sel ? 64 : H;
    float* Xp = sel ? g_t2 : g_t1;
    int f = blockIdx.x;
    int t = threadIdx.x;   // 64 threads
    __shared__ float sh[64];
    float s = 0.0f;
    for (int r = t; r < G; r += 64) s += Xp[r*F + f];
    sh[t] = s; __syncthreads();
    for (int st = 32; st > 0; st >>= 1) { if (t < st) sh[t] += sh[t + st]; __syncthreads(); }
    float mean = sh[0] / (float)G;
    __syncthreads();
    float v = 0.0f;
    for (int r = t; r < G; r += 64) { float d = Xp[r*F + f] - mean; v += d * d; }
    sh[t] = v; __syncthreads();
    for (int st = 32; st > 0; st >>= 1) { if (t < st) sh[t] += sh[t + st]; __syncthreads(); }
    float inv = 1.0f / sqrtf(sh[0] / (float)G + EPS);
    float gg = gam[f], bb = bet[f];
    for (int r = t; r < G; r += 64) {
        float y = (Xp[r*F + f] - mean) * inv * gg + bb;
        Xp[r*F + f] = fmaxf(y, 0.0f);
    }
}
__global__ void k_final(float* __restrict__ out,
                        const float* __restrict__ W,
                        const float* __restrict__ b) {
    int r = blockIdx.x * blockDim.x + threadIdx.x;
    if (r < G) {
        float l0 = b[0], l1 = b[1];
        for (int f = 0; f < 64; f++) {
            float v = g_t2[r*64 + f];
            l0 += v * W[f];
            l1 += v * W[64 + f];
        }
        float m = fmaxf(l0, l1);
        float e0 = expf(l0 - m), e1 = expf(l1 - m);
        float sum = e0 + e1;
        out[r*2]     = e0 / sum;
        out[r*2 + 1] = e1 / sum;
    }
}

// ---------------- launch sequence ----------------
extern "C" void kernel_launch(void* const* d_in, const int* in_sizes, int n_in,
                              void* d_out, int out_size) {
    const float* x      = (const float*)d_in[0];
    const int*   ei     = (const int*)  d_in[1];
    const float* Wrel1  = (const float*)d_in[2];
    const float* Wroot1 = (const float*)d_in[3];
    const float* b1     = (const float*)d_in[4];
    const float* Wrel2  = (const float*)d_in[5];
    const float* Wroot2 = (const float*)d_in[6];
    const float* b2     = (const float*)d_in[7];
    const float* Wrel3  = (const float*)d_in[8];
    const float* Wroot3 = (const float*)d_in[9];
    const float* b3     = (const float*)d_in[10];
    const float* pw1    = (const float*)d_in[11];
    const float* pw2    = (const float*)d_in[12];
    const float* pw3    = (const float*)d_in[13];
    const float* lin1_w = (const float*)d_in[14];
    const float* lin1_b = (const float*)d_in[15];
    const float* lin2_w = (const float*)d_in[16];
    const float* lin2_b = (const float*)d_in[17];
    const float* lin3_w = (const float*)d_in[18];
    const float* lin3_b = (const float*)d_in[19];
    const float* bn1_g  = (const float*)d_in[20];
    const float* bn1_b  = (const float*)d_in[21];
    const float* bn2_g  = (const float*)d_in[22];
    const float* bn2_b  = (const float*)d_in[23];
    float* out = (float*)d_out;

    // CSR build + init
    k_init<<<(NN + 255)/256, 256>>>(pw1, pw2, pw3);
    k_hist<<<(ET + 255)/256, 256>>>(ei);
    k_scan1<<<100, 1024>>>();
    k_scan3<<<100, 1024>>>();
    k_fill<<<(ET + 255)/256, 256>>>(ei);

    // level 1
    k_conv1f<<<NN, H>>>(x, Wrel1, Wroot1, b1, pw1);
    k_rank<<<G, 512>>>(N0, K1);
    k_copy<<<G*K1, H>>>(N0, K1);
    k_readout<<<G, 512>>>(K1, 1);
    k_gather<<<G*K1, H>>>();

    // level 2
    const int n2 = G * K1;
    k_convH<<<(n2 + 63)/64, 256>>>(n2, Wrel2, Wroot2, b2, pw2, 1);
    k_rank<<<G, 512>>>(K1, K2);
    k_copy<<<G*K2, H>>>(K1, K2);
    k_readout<<<G, 512>>>(K2, 0);
    k_gather<<<G*K2, H>>>();

    // level 3
    const int n3 = G * K2;
    k_convH<<<(n3 + 63)/64, 256>>>(n3, Wrel3, Wroot3, b3, pw3, 2);
    k_rank<<<G, 512>>>(K2, K3);
    k_copy<<<G*K3, H>>>(K2, K3);
    k_readout<<<G, 512>>>(K3, 0);

    // MLP head
    k_fc1<<<dim3(16, 50), 256>>>(lin1_w, lin1_b);
    k_bn_relu<<<H, 64>>>(0, bn1_g, bn1_b);
    k_fc2<<<dim3(8, 25), 256>>>(lin2_w, lin2_b);
    k_bn_relu<<<64, 64>>>(1, bn2_g, bn2_b);
    k_final<<<(G + 127)/128, 128>>>(out, lin3_w, lin3_b);
}